// round 4
// baseline (speedup 1.0000x reference)
#include <cuda_runtime.h>
#include <math.h>

// Problem constants
#define BB    4
#define SS    128
#define LL    2304          // SEQ + 2S
#define DIN   512
#define DK    64
#define NROW  (BB*LL)       // 9216
#define MIDLO SS            // 128
#define MIDHI (LL-SS)       // 2176
#define SCALE 0.125f        // 1/sqrt(64)

// Scratch: projected Q/K/V for all rows (q_full/k_full/v_full layout == row order)
__device__ float g_Q[NROW*DK];
__device__ float g_K[NROW*DK];
__device__ float g_V[NROW*DK];

// ---------------------------------------------------------------------------
// Kernel 1: LayerNorm + QKV projection.  8 rows per CTA (amortize weight reads).
// Warp w normalizes row r0+w into SMEM; then threads 0..191 each own one output
// column (64 Q / 64 K / 64 V) and compute dots for all 8 rows sharing one
// weight load per i (8x weight reuse).
// ---------------------------------------------------------------------------
__global__ __launch_bounds__(256) void ln_proj_kernel(
    const float* __restrict__ x,
    const float* __restrict__ Wq,  const float* __restrict__ Wk,  const float* __restrict__ Wv,
    const float* __restrict__ Wqs, const float* __restrict__ Wks, const float* __restrict__ Wvs,
    const float* __restrict__ Wqe, const float* __restrict__ Wke, const float* __restrict__ Wve,
    const float* __restrict__ lg,  const float* __restrict__ lb,
    const float* __restrict__ lsg, const float* __restrict__ lsb,
    const float* __restrict__ leg, const float* __restrict__ leb)
{
    __shared__ float xn[8*DIN];                  // 16 KB normalized rows
    const int tid  = threadIdx.x;
    const int w    = tid >> 5;
    const int lane = tid & 31;
    const int r0   = blockIdx.x * 8;             // 8 consecutive rows, never straddle
    const int rloc = r0 % LL;                    // segment boundaries are %8 == 0
    const int seg  = (rloc < SS) ? 1 : (rloc >= MIDHI ? 2 : 0);   // 0=mid 1=start 2=end

    const float* g  = seg==0 ? lg : (seg==1 ? lsg : leg);
    const float* be = seg==0 ? lb : (seg==1 ? lsb : leb);

    // --- LayerNorm (warp w -> row r0+w) ---
    {
        const float* xr = x + (size_t)(r0 + w) * DIN;
        float s = 0.f, s2 = 0.f;
        for (int i = lane; i < DIN; i += 32) { float v = xr[i]; s += v; s2 += v*v; }
        #pragma unroll
        for (int o = 16; o; o >>= 1) {
            s  += __shfl_xor_sync(0xffffffffu, s,  o);
            s2 += __shfl_xor_sync(0xffffffffu, s2, o);
        }
        const float mean = s * (1.0f/DIN);
        const float var  = s2 * (1.0f/DIN) - mean*mean;
        const float rstd = rsqrtf(var + 1e-5f);
        for (int i = lane; i < DIN; i += 32)
            xn[w*DIN + i] = (xr[i] - mean) * rstd * g[i] + be[i];
    }
    __syncthreads();

    // --- Projections: 192 output columns, 8 rows each ---
    if (tid < 192) {
        const float* W; float* dst; int col;
        if (tid < 64)       { W = seg==0 ? Wq : (seg==1 ? Wqs : Wqe); dst = g_Q; col = tid; }
        else if (tid < 128) { W = seg==0 ? Wk : (seg==1 ? Wks : Wke); dst = g_K; col = tid - 64; }
        else                { W = seg==0 ? Wv : (seg==1 ? Wvs : Wve); dst = g_V; col = tid - 128; }

        float acc[8] = {0.f,0.f,0.f,0.f,0.f,0.f,0.f,0.f};
        #pragma unroll 4
        for (int i = 0; i < DIN; i++) {
            const float wv = W[i*DK + col];       // coalesced across lanes
            #pragma unroll
            for (int r = 0; r < 8; r++) acc[r] += xn[r*DIN + i] * wv;  // SMEM broadcast
        }
        #pragma unroll
        for (int r = 0; r < 8; r++) dst[(size_t)(r0 + r)*DK + col] = acc[r];
    }
}

// ---------------------------------------------------------------------------
// Kernel 2: fused CoPE-gated causal attention.
//  - CTA: 8 q rows (one warp each), 256 threads.
//  - K tiles of 32, iterated DESCENDING so the reverse cumsum of gates is a
//    running carry + warp prefix scan (lane order = descending k).
//  - gate logit == unscaled score dot (middle x middle), computed once.
//  - Online softmax per warp; 64-wide accumulator distributed 2 regs/lane.
// ---------------------------------------------------------------------------
#define KPAD 33
__global__ __launch_bounds__(256) void attn_kernel(
    const float* __restrict__ cope,     // [64][128] row-major
    float* __restrict__ out)            // [B][L][64]
{
    __shared__ float Ksm[DK*KPAD];      // K tile transposed [d][kk], padded
    __shared__ float Vsm[32*DK];        // V tile [kk][d]
    __shared__ float Qs [8*DK];         // 8 q rows
    __shared__ float Csm[8*SS];         // cope logits per q row (mid CTAs only)
    __shared__ float psm[8*32];         // per-warp probability strip

    const int tid  = threadIdx.x;
    const int w    = tid >> 5;
    const int lane = tid & 31;
    const int b    = blockIdx.y;
    const int q0   = blockIdx.x * 8;
    const int qrow = q0 + w;
    const int bL   = b * LL;
    const bool midq = (q0 >= MIDLO) && (q0 < MIDHI);   // uniform within CTA
    const int qmax  = q0 + 7;

    // Load Q tile
    for (int i = tid; i < 8*DK; i += 256)
        Qs[i] = g_Q[(size_t)(bL + q0)*DK + i];
    __syncthreads();

    // CoPE logits: c[j] = q . cope[:, j], 128 per mid q row
    if (midq) {
        for (int jj = lane; jj < SS; jj += 32) {
            float c = 0.f;
            #pragma unroll
            for (int d = 0; d < DK; d++) c += Qs[w*DK + d] * cope[d*SS + jj];
            Csm[w*SS + jj] = c;
        }
    }

    float m = -1e30f, l = 0.f, acc0 = 0.f, acc1 = 0.f, carry = 0.f;
    const int t_hi = midq ? (MIDHI/32 - 1) : (qmax >> 5);

    for (int t = t_hi; t >= 0; t--) {
        const int  kb       = t * 32;
        const bool tile_mid = (kb >= MIDLO) && (kb < MIDHI);   // tiles never straddle
        const bool anyscore = (kb <= qmax);

        __syncthreads();                      // protect previous tile's SMEM reads
        for (int i = tid; i < 32*DK; i += 256) {
            const int kk = i >> 6, d = i & 63;
            Ksm[d*KPAD + kk] = g_K[(size_t)(bL + kb + kk)*DK + d];
        }
        if (anyscore) {
            for (int i = tid; i < 32*DK; i += 256) {
                const int kk = i >> 6, d = i & 63;
                Vsm[i] = g_V[(size_t)(bL + kb + kk)*DK + d];
            }
        }
        __syncthreads();

        const bool need_gate = midq && tile_mid;   // gates over ALL middle k (non-causal)
        const bool wscore    = (kb <= qrow);       // per-warp causal reach into this tile
        if (!need_gate && !wscore) continue;       // syncs above already passed

        const int kkl   = 31 - lane;               // tile-local k, descending across lanes
        const int kglob = kb + kkl;

        float dot = 0.f;
        #pragma unroll
        for (int d = 0; d < DK; d++)
            dot += Qs[w*DK + d] * Ksm[d*KPAD + kkl];   // Qs broadcast, Ksm conflict-free

        float pos = 0.f;
        if (need_gate) {
            const float gg = 1.f / (1.f + expf(-dot));
            float pref = gg;
            #pragma unroll
            for (int o = 1; o < 32; o <<= 1) {         // inclusive prefix over lanes
                const float nv = __shfl_up_sync(0xffffffffu, pref, o);
                if (lane >= o) pref += nv;
            }
            pos = carry + pref;                        // suffix sum over k >= kglob
            carry += __shfl_sync(0xffffffffu, pref, 31);
        }

        if (wscore) {
            const bool active = (kglob <= qrow);
            float s = -1e30f;
            if (active) {
                s = dot * SCALE;
                if (need_gate) {
                    const float pc  = fminf(pos, (float)(SS-1));
                    const float pf  = floorf(pc);
                    const int   ic  = (int)ceilf(pc);
                    const int   ifl = (int)pf;
                    const float wf  = pc - pf;
                    s += Csm[w*SS + ic]*wf + Csm[w*SS + ifl]*(1.f - wf);
                }
            }
            float tmax = s;
            #pragma unroll
            for (int o = 16; o; o >>= 1) tmax = fmaxf(tmax, __shfl_xor_sync(0xffffffffu, tmax, o));
            const float mnew  = fmaxf(m, tmax);
            const float alpha = expf(m - mnew);        // 0 on first tile (m = -1e30)
            const float p     = expf(s - mnew);        // 0 for masked lanes
            float ps = p;
            #pragma unroll
            for (int o = 16; o; o >>= 1) ps += __shfl_xor_sync(0xffffffffu, ps, o);
            l = l*alpha + ps;
            acc0 *= alpha; acc1 *= alpha;
            m = mnew;

            psm[w*32 + kkl] = p;                       // warp-private strip
            __syncwarp();
            #pragma unroll
            for (int kk = 0; kk < 32; kk++) {
                const float pv = psm[w*32 + kk];
                acc0 += pv * Vsm[kk*DK + lane];
                acc1 += pv * Vsm[kk*DK + lane + 32];
            }
            __syncwarp();
        }
    }

    const float inv = 1.f / l;
    const size_t o = (size_t)(bL + qrow) * DK;
    out[o + lane]      = acc0 * inv;
    out[o + lane + 32] = acc1 * inv;
}

// ---------------------------------------------------------------------------
extern "C" void kernel_launch(void* const* d_in, const int* in_sizes, int n_in,
                              void* d_out, int out_size)
{
    const float* x    = (const float*)d_in[0];
    const float* Wq   = (const float*)d_in[1];
    const float* Wk   = (const float*)d_in[2];
    const float* Wv   = (const float*)d_in[3];
    const float* Wqs  = (const float*)d_in[4];
    const float* Wks  = (const float*)d_in[5];
    const float* Wvs  = (const float*)d_in[6];
    const float* Wqe  = (const float*)d_in[7];
    const float* Wke  = (const float*)d_in[8];
    const float* Wve  = (const float*)d_in[9];
    const float* lg   = (const float*)d_in[10];
    const float* lb   = (const float*)d_in[11];
    const float* lsg  = (const float*)d_in[12];
    const float* lsb  = (const float*)d_in[13];
    const float* leg  = (const float*)d_in[14];
    const float* leb  = (const float*)d_in[15];
    const float* cope = (const float*)d_in[16];
    float* out = (float*)d_out;

    ln_proj_kernel<<<NROW/8, 256>>>(x, Wq, Wk, Wv, Wqs, Wks, Wvs, Wqe, Wke, Wve,
                                    lg, lb, lsg, lsb, leg, leb);
    attn_kernel<<<dim3(LL/8, BB), 256>>>(cope, out);
}

// round 8
// speedup vs baseline: 1.6700x; 1.6700x over previous
#include <cuda_runtime.h>
#include <math.h>

// Problem constants
#define BB    4
#define SS    128
#define LL    2304          // SEQ + 2S
#define DIN   512
#define DK    64
#define NROW  (BB*LL)       // 9216
#define MIDLO SS            // 128
#define MIDHI (LL-SS)       // 2176
#define SCALE 0.125f        // 1/sqrt(64)

// Scratch: projected Q/K/V for all rows
__device__ float g_Q[NROW*DK];
__device__ float g_K[NROW*DK];
__device__ float g_V[NROW*DK];

// ---------------------------------------------------------------------------
// Kernel 1: LayerNorm + QKV projection. 8 rows per CTA, 8x weight reuse.
// ---------------------------------------------------------------------------
__global__ __launch_bounds__(256) void ln_proj_kernel(
    const float* __restrict__ x,
    const float* __restrict__ Wq,  const float* __restrict__ Wk,  const float* __restrict__ Wv,
    const float* __restrict__ Wqs, const float* __restrict__ Wks, const float* __restrict__ Wvs,
    const float* __restrict__ Wqe, const float* __restrict__ Wke, const float* __restrict__ Wve,
    const float* __restrict__ lg,  const float* __restrict__ lb,
    const float* __restrict__ lsg, const float* __restrict__ lsb,
    const float* __restrict__ leg, const float* __restrict__ leb)
{
    __shared__ float xn[8*DIN];
    const int tid  = threadIdx.x;
    const int w    = tid >> 5;
    const int lane = tid & 31;
    const int r0   = blockIdx.x * 8;
    const int rloc = r0 % LL;
    const int seg  = (rloc < SS) ? 1 : (rloc >= MIDHI ? 2 : 0);

    const float* g  = seg==0 ? lg : (seg==1 ? lsg : leg);
    const float* be = seg==0 ? lb : (seg==1 ? lsb : leb);

    {
        const float* xr = x + (size_t)(r0 + w) * DIN;
        float s = 0.f, s2 = 0.f;
        for (int i = lane; i < DIN; i += 32) { float v = xr[i]; s += v; s2 += v*v; }
        #pragma unroll
        for (int o = 16; o; o >>= 1) {
            s  += __shfl_xor_sync(0xffffffffu, s,  o);
            s2 += __shfl_xor_sync(0xffffffffu, s2, o);
        }
        const float mean = s * (1.0f/DIN);
        const float var  = s2 * (1.0f/DIN) - mean*mean;
        const float rstd = rsqrtf(var + 1e-5f);
        for (int i = lane; i < DIN; i += 32)
            xn[w*DIN + i] = (xr[i] - mean) * rstd * g[i] + be[i];
    }
    __syncthreads();

    if (tid < 192) {
        const float* W; float* dst; int col;
        if (tid < 64)       { W = seg==0 ? Wq : (seg==1 ? Wqs : Wqe); dst = g_Q; col = tid; }
        else if (tid < 128) { W = seg==0 ? Wk : (seg==1 ? Wks : Wke); dst = g_K; col = tid - 64; }
        else                { W = seg==0 ? Wv : (seg==1 ? Wvs : Wve); dst = g_V; col = tid - 128; }

        float acc[8] = {0.f,0.f,0.f,0.f,0.f,0.f,0.f,0.f};
        #pragma unroll 4
        for (int i = 0; i < DIN; i++) {
            const float wv = W[i*DK + col];
            #pragma unroll
            for (int r = 0; r < 8; r++) acc[r] += xn[r*DIN + i] * wv;
        }
        #pragma unroll
        for (int r = 0; r < 8; r++) dst[(size_t)(r0 + r)*DK + col] = acc[r];
    }
}

// ---------------------------------------------------------------------------
// Kernel 2: fused CoPE-gated causal attention, register-tiled.
//  - CTA: 32 q rows; warp = 4 q rows; 256 threads.
//  - k-tiles of 32 in DESCENDING order (reverse cumsum of gates = carry +
//    warp inclusive prefix over lanes, lane order = descending k).
//  - Score dot: vectorized LDS.128 for K column + Q broadcast; 4 rows share
//    every K read.
//  - PV: V LDS.64 shared by 4 rows; p exchanged via one STS.128 per lane.
//  - Fully uniform control flow (no continue), identical barrier count on
//    every path.
// ---------------------------------------------------------------------------
#define KROW 68                       // padded K row (floats): conflict-free LDS.128
__global__ __launch_bounds__(256, 2) void attn_kernel(
    const float* __restrict__ cope,   // [64][128] row-major
    float* __restrict__ out)          // [B][L][64]
{
    __shared__ float Ksm[32*KROW];    // K tile [kk][d], padded        (8.5 KB)
    __shared__ float Vsm[32*DK];      // V tile [kk][d]                (8 KB)
    __shared__ float Qs [32*DK];      // 32 q rows                     (8 KB)
    __shared__ float Csm[32*SS];      // cope logits per q row         (16 KB)
    __shared__ float Psm[8][32][4];   // [warp][kk][r] prob strip      (4 KB)

    const int tid  = threadIdx.x;
    const int w    = tid >> 5;
    const int lane = tid & 31;
    const int b    = blockIdx.y;
    const int q0   = blockIdx.x * 32;
    const int bL   = b * LL;
    const bool midq = (q0 >= MIDLO) && (q0 < MIDHI);   // uniform within CTA
    const int wq0l  = w * 4;             // first local q row of this warp
    const int wq0g  = q0 + wq0l;         // first global q row of this warp
    const int qg3   = wq0g + 3;          // last q row of this warp
    const int qmaxc = q0 + 31;           // last q row of CTA

    // Load Q tile (32x64 floats = 512 float4)
    for (int i = tid; i < 512; i += 256) {
        const int row = i >> 4, d4 = (i & 15) << 2;
        *(float4*)&Qs[row*DK + d4] =
            *(const float4*)&g_Q[(size_t)(bL + q0 + row)*DK + d4];
    }
    __syncthreads();

    // CoPE logits for this warp's 4 rows: Csm[r][j] = q_r . cope[:, j]
    if (midq) {
        float4 ca[4] = {{0,0,0,0},{0,0,0,0},{0,0,0,0},{0,0,0,0}};
        const int j4 = lane * 4;
        #pragma unroll 4
        for (int d = 0; d < DK; d++) {
            const float4 cv = *(const float4*)&cope[d*SS + j4];
            #pragma unroll
            for (int r = 0; r < 4; r++) {
                const float qd = Qs[(wq0l + r)*DK + d];
                ca[r].x += qd*cv.x; ca[r].y += qd*cv.y;
                ca[r].z += qd*cv.z; ca[r].w += qd*cv.w;
            }
        }
        #pragma unroll
        for (int r = 0; r < 4; r++)
            *(float4*)&Csm[(wq0l + r)*SS + j4] = ca[r];
    }

    float m[4]     = {-1e30f,-1e30f,-1e30f,-1e30f};
    float l[4]     = {0.f,0.f,0.f,0.f};
    float carry[4] = {0.f,0.f,0.f,0.f};
    float acc[4][2] = {{0.f,0.f},{0.f,0.f},{0.f,0.f},{0.f,0.f}};

    const int t_hi = midq ? (MIDHI/32 - 1) : (qmaxc >> 5);
    const int kkl   = 31 - lane;           // tile-local k, descending across lanes

    for (int t = t_hi; t >= 0; t--) {
        const int  kb       = t * 32;
        const bool tile_mid = (kb >= MIDLO);            // t_hi caps kb < MIDHI
        const bool ctascore = (kb <= qmaxc);

        __syncthreads();                   // protect previous tile's SMEM reads
        for (int i = tid; i < 512; i += 256) {
            const int kk = i >> 4, d4 = (i & 15) << 2;
            *(float4*)&Ksm[kk*KROW + d4] =
                *(const float4*)&g_K[(size_t)(bL + kb + kk)*DK + d4];
            if (ctascore)
                *(float4*)&Vsm[kk*DK + d4] =
                    *(const float4*)&g_V[(size_t)(bL + kb + kk)*DK + d4];
        }
        __syncthreads();

        const bool need_gate = midq && tile_mid;        // gates: ALL middle k (CTA-uniform)
        const bool anyw      = (kb <= qg3);             // warp scores this tile (warp-uniform)

        if (need_gate || anyw) {
            // ---- score dots for 4 rows (K read once, shared by rows) ----
            float dot[4] = {0.f,0.f,0.f,0.f};
            {
                const float4* kp = (const float4*)&Ksm[kkl*KROW];
                #pragma unroll
                for (int c = 0; c < 16; c++) {
                    const float4 kv = kp[c];
                    #pragma unroll
                    for (int r = 0; r < 4; r++) {
                        const float4 qv = *(const float4*)&Qs[(wq0l + r)*DK + c*4];
                        dot[r] += kv.x*qv.x + kv.y*qv.y + kv.z*qv.z + kv.w*qv.w;
                    }
                }
            }

            // ---- gate suffix-sum (reverse cumsum over k) ----
            float pos[4] = {0.f,0.f,0.f,0.f};
            if (need_gate) {
                #pragma unroll
                for (int r = 0; r < 4; r++) {
                    const float gg = 1.f / (1.f + __expf(-dot[r]));
                    float pref = gg;
                    #pragma unroll
                    for (int o = 1; o < 32; o <<= 1) {
                        const float nv = __shfl_up_sync(0xffffffffu, pref, o);
                        if (lane >= o) pref += nv;
                    }
                    pos[r] = carry[r] + pref;
                    carry[r] += __shfl_sync(0xffffffffu, pref, 31);
                }
            }

            // ---- online softmax + PV ----
            if (anyw) {
                const int kglob = kb + kkl;
                float p[4];
                #pragma unroll
                for (int r = 0; r < 4; r++) {
                    const int qr = wq0g + r;
                    const bool rowactive = (kb <= qr);      // warp-uniform
                    float s = -1e30f;
                    if (rowactive && kglob <= qr) {
                        s = dot[r] * SCALE;
                        if (need_gate) {
                            const float pc  = fminf(pos[r], (float)(SS-1));
                            const float pf  = floorf(pc);
                            const int   ic  = (int)ceilf(pc);
                            const int   ifl = (int)pf;
                            const float wf  = pc - pf;
                            const float* cr = &Csm[(wq0l + r)*SS];
                            s += cr[ic]*wf + cr[ifl]*(1.f - wf);
                        }
                    }
                    float tmax = s;
                    #pragma unroll
                    for (int o = 16; o; o >>= 1)
                        tmax = fmaxf(tmax, __shfl_xor_sync(0xffffffffu, tmax, o));
                    if (rowactive) {
                        const float mnew  = fmaxf(m[r], tmax);
                        const float alpha = __expf(m[r] - mnew);
                        const float pr    = __expf(s - mnew);   // 0 for masked lanes
                        float ps = pr;
                        #pragma unroll
                        for (int o = 16; o; o >>= 1)
                            ps += __shfl_xor_sync(0xffffffffu, ps, o);
                        l[r] = l[r]*alpha + ps;
                        acc[r][0] *= alpha; acc[r][1] *= alpha;
                        m[r] = mnew;
                        p[r] = pr;
                    } else {
                        p[r] = 0.f;
                    }
                }

                *(float4*)&Psm[w][kkl][0] = make_float4(p[0], p[1], p[2], p[3]);
                __syncwarp();
                const int d2 = 2*lane;
                #pragma unroll
                for (int kk = 0; kk < 32; kk++) {
                    const float4 pv = *(const float4*)&Psm[w][kk][0];  // broadcast
                    const float2 vv = *(const float2*)&Vsm[kk*DK + d2];
                    acc[0][0] += pv.x*vv.x; acc[0][1] += pv.x*vv.y;
                    acc[1][0] += pv.y*vv.x; acc[1][1] += pv.y*vv.y;
                    acc[2][0] += pv.z*vv.x; acc[2][1] += pv.z*vv.y;
                    acc[3][0] += pv.w*vv.x; acc[3][1] += pv.w*vv.y;
                }
                __syncwarp();
            }
        }
    }

    #pragma unroll
    for (int r = 0; r < 4; r++) {
        const float inv = 1.f / l[r];
        float2 o2; o2.x = acc[r][0]*inv; o2.y = acc[r][1]*inv;
        *(float2*)&out[(size_t)(bL + wq0g + r)*DK + 2*lane] = o2;
    }
}

// ---------------------------------------------------------------------------
extern "C" void kernel_launch(void* const* d_in, const int* in_sizes, int n_in,
                              void* d_out, int out_size)
{
    const float* x    = (const float*)d_in[0];
    const float* Wq   = (const float*)d_in[1];
    const float* Wk   = (const float*)d_in[2];
    const float* Wv   = (const float*)d_in[3];
    const float* Wqs  = (const float*)d_in[4];
    const float* Wks  = (const float*)d_in[5];
    const float* Wvs  = (const float*)d_in[6];
    const float* Wqe  = (const float*)d_in[7];
    const float* Wke  = (const float*)d_in[8];
    const float* Wve  = (const float*)d_in[9];
    const float* lg   = (const float*)d_in[10];
    const float* lb   = (const float*)d_in[11];
    const float* lsg  = (const float*)d_in[12];
    const float* lsb  = (const float*)d_in[13];
    const float* leg  = (const float*)d_in[14];
    const float* leb  = (const float*)d_in[15];
    const float* cope = (const float*)d_in[16];
    float* out = (float*)d_out;

    ln_proj_kernel<<<NROW/8, 256>>>(x, Wq, Wk, Wv, Wqs, Wks, Wvs, Wqe, Wke, Wve,
                                    lg, lb, lsg, lsb, leg, leb);
    attn_kernel<<<dim3(LL/32, BB), 256>>>(cope, out);
}

// round 9
// speedup vs baseline: 1.7971x; 1.0762x over previous
#include <cuda_runtime.h>
#include <math.h>

// Problem constants
#define BB    4
#define SS    128
#define LL    2304          // SEQ + 2S
#define DIN   512
#define DK    64
#define NROW  (BB*LL)       // 9216
#define MIDLO SS            // 128
#define MIDHI (LL-SS)       // 2176
#define SCALE 0.125f        // 1/sqrt(64)

// Scratch: projected Q/K/V for all rows
__device__ float g_Q[NROW*DK];
__device__ float g_K[NROW*DK];
__device__ float g_V[NROW*DK];

// ---------------------------------------------------------------------------
// Kernel 1: LayerNorm + QKV projection. 16 rows per CTA (16x weight reuse,
// half the L2 weight traffic of the 8-row version), float4 xn reads.
// ---------------------------------------------------------------------------
#define RPC 16
__global__ __launch_bounds__(256) void ln_proj_kernel(
    const float* __restrict__ x,
    const float* __restrict__ Wq,  const float* __restrict__ Wk,  const float* __restrict__ Wv,
    const float* __restrict__ Wqs, const float* __restrict__ Wks, const float* __restrict__ Wvs,
    const float* __restrict__ Wqe, const float* __restrict__ Wke, const float* __restrict__ Wve,
    const float* __restrict__ lg,  const float* __restrict__ lb,
    const float* __restrict__ lsg, const float* __restrict__ lsb,
    const float* __restrict__ leg, const float* __restrict__ leb)
{
    __shared__ float xn[RPC*DIN];                // 32 KB normalized rows
    const int tid  = threadIdx.x;
    const int w    = tid >> 5;
    const int lane = tid & 31;
    const int r0   = blockIdx.x * RPC;           // segment bounds are %16 == 0
    const int rloc = r0 % LL;
    const int seg  = (rloc < SS) ? 1 : (rloc >= MIDHI ? 2 : 0);

    const float* g  = seg==0 ? lg : (seg==1 ? lsg : leg);
    const float* be = seg==0 ? lb : (seg==1 ? lsb : leb);

    // --- LayerNorm: warp w handles rows 2w, 2w+1 ---
    #pragma unroll
    for (int rr = 0; rr < 2; rr++) {
        const int rl = w*2 + rr;
        const float* xr = x + (size_t)(r0 + rl) * DIN;
        float s = 0.f, s2 = 0.f;
        for (int i = lane; i < DIN; i += 32) { float v = xr[i]; s += v; s2 += v*v; }
        #pragma unroll
        for (int o = 16; o; o >>= 1) {
            s  += __shfl_xor_sync(0xffffffffu, s,  o);
            s2 += __shfl_xor_sync(0xffffffffu, s2, o);
        }
        const float mean = s * (1.0f/DIN);
        const float var  = s2 * (1.0f/DIN) - mean*mean;
        const float rstd = rsqrtf(var + 1e-5f);
        for (int i = lane; i < DIN; i += 32)
            xn[rl*DIN + i] = (xr[i] - mean) * rstd * g[i] + be[i];
    }
    __syncthreads();

    // --- Projections: 192 output columns, 16 rows each ---
    if (tid < 192) {
        const float* W; float* dst; int col;
        if (tid < 64)       { W = seg==0 ? Wq : (seg==1 ? Wqs : Wqe); dst = g_Q; col = tid; }
        else if (tid < 128) { W = seg==0 ? Wk : (seg==1 ? Wks : Wke); dst = g_K; col = tid - 64; }
        else                { W = seg==0 ? Wv : (seg==1 ? Wvs : Wve); dst = g_V; col = tid - 128; }

        float acc[RPC];
        #pragma unroll
        for (int r = 0; r < RPC; r++) acc[r] = 0.f;

        for (int i4 = 0; i4 < DIN/4; i4++) {
            const int i = i4 * 4;
            const float w0 = W[(i+0)*DK + col];   // coalesced across lanes
            const float w1 = W[(i+1)*DK + col];
            const float w2 = W[(i+2)*DK + col];
            const float w3 = W[(i+3)*DK + col];
            #pragma unroll
            for (int r = 0; r < RPC; r++) {
                const float4 x4 = *(const float4*)&xn[r*DIN + i];   // LDS.128 broadcast
                acc[r] += x4.x*w0 + x4.y*w1 + x4.z*w2 + x4.w*w3;
            }
        }
        #pragma unroll
        for (int r = 0; r < RPC; r++) dst[(size_t)(r0 + r)*DK + col] = acc[r];
    }
}

// ---------------------------------------------------------------------------
// Kernel 2: fused CoPE-gated causal attention, register-tiled.
//  - CTA: 32 q rows; warp = 4 q rows; 256 threads; 3 CTAs/SM target.
//  - k-tiles of 32 in DESCENDING order (reverse cumsum of gates = carry +
//    warp inclusive prefix over lanes, lane order = descending k).
// ---------------------------------------------------------------------------
#define KROW 68                       // padded K row (floats): conflict-free LDS.128
__global__ __launch_bounds__(256, 3) void attn_kernel(
    const float* __restrict__ cope,   // [64][128] row-major
    float* __restrict__ out)          // [B][L][64]
{
    __shared__ float Ksm[32*KROW];    // K tile [kk][d], padded        (8.5 KB)
    __shared__ float Vsm[32*DK];      // V tile [kk][d]                (8 KB)
    __shared__ float Qs [32*DK];      // 32 q rows                     (8 KB)
    __shared__ float Csm[32*SS];      // cope logits per q row         (16 KB)
    __shared__ float Psm[8][32][4];   // [warp][kk][r] prob strip      (4 KB)

    const int tid  = threadIdx.x;
    const int w    = tid >> 5;
    const int lane = tid & 31;
    const int b    = blockIdx.y;
    const int q0   = blockIdx.x * 32;
    const int bL   = b * LL;
    const bool midq = (q0 >= MIDLO) && (q0 < MIDHI);   // uniform within CTA
    const int wq0l  = w * 4;             // first local q row of this warp
    const int wq0g  = q0 + wq0l;         // first global q row of this warp
    const int qg3   = wq0g + 3;          // last q row of this warp
    const int qmaxc = q0 + 31;           // last q row of CTA

    // Load Q tile (32x64 floats = 512 float4)
    for (int i = tid; i < 512; i += 256) {
        const int row = i >> 4, d4 = (i & 15) << 2;
        *(float4*)&Qs[row*DK + d4] =
            *(const float4*)&g_Q[(size_t)(bL + q0 + row)*DK + d4];
    }
    __syncthreads();

    // CoPE logits for this warp's 4 rows: Csm[r][j] = q_r . cope[:, j]
    if (midq) {
        float4 ca[4] = {{0,0,0,0},{0,0,0,0},{0,0,0,0},{0,0,0,0}};
        const int j4 = lane * 4;
        #pragma unroll 4
        for (int d = 0; d < DK; d++) {
            const float4 cv = *(const float4*)&cope[d*SS + j4];
            #pragma unroll
            for (int r = 0; r < 4; r++) {
                const float qd = Qs[(wq0l + r)*DK + d];
                ca[r].x += qd*cv.x; ca[r].y += qd*cv.y;
                ca[r].z += qd*cv.z; ca[r].w += qd*cv.w;
            }
        }
        #pragma unroll
        for (int r = 0; r < 4; r++)
            *(float4*)&Csm[(wq0l + r)*SS + j4] = ca[r];
    }

    float m[4]     = {-1e30f,-1e30f,-1e30f,-1e30f};
    float l[4]     = {0.f,0.f,0.f,0.f};
    float carry[4] = {0.f,0.f,0.f,0.f};
    float acc[4][2] = {{0.f,0.f},{0.f,0.f},{0.f,0.f},{0.f,0.f}};

    const int t_hi = midq ? (MIDHI/32 - 1) : (qmaxc >> 5);
    const int kkl   = 31 - lane;           // tile-local k, descending across lanes

    for (int t = t_hi; t >= 0; t--) {
        const int  kb       = t * 32;
        const bool tile_mid = (kb >= MIDLO);            // t_hi caps kb < MIDHI
        const bool ctascore = (kb <= qmaxc);

        __syncthreads();                   // protect previous tile's SMEM reads
        for (int i = tid; i < 512; i += 256) {
            const int kk = i >> 4, d4 = (i & 15) << 2;
            *(float4*)&Ksm[kk*KROW + d4] =
                *(const float4*)&g_K[(size_t)(bL + kb + kk)*DK + d4];
            if (ctascore)
                *(float4*)&Vsm[kk*DK + d4] =
                    *(const float4*)&g_V[(size_t)(bL + kb + kk)*DK + d4];
        }
        __syncthreads();

        const bool need_gate = midq && tile_mid;        // gates: ALL middle k (CTA-uniform)
        const bool anyw      = (kb <= qg3);             // warp scores this tile (warp-uniform)

        if (need_gate || anyw) {
            // ---- score dots for 4 rows (K read once, shared by rows) ----
            float dot[4] = {0.f,0.f,0.f,0.f};
            {
                const float4* kp = (const float4*)&Ksm[kkl*KROW];
                #pragma unroll 8
                for (int c = 0; c < 16; c++) {
                    const float4 kv = kp[c];
                    #pragma unroll
                    for (int r = 0; r < 4; r++) {
                        const float4 qv = *(const float4*)&Qs[(wq0l + r)*DK + c*4];
                        dot[r] += kv.x*qv.x + kv.y*qv.y + kv.z*qv.z + kv.w*qv.w;
                    }
                }
            }

            // ---- gate suffix-sum (reverse cumsum over k) ----
            float pos[4] = {0.f,0.f,0.f,0.f};
            if (need_gate) {
                #pragma unroll
                for (int r = 0; r < 4; r++) {
                    const float gg = 1.f / (1.f + __expf(-dot[r]));
                    float pref = gg;
                    #pragma unroll
                    for (int o = 1; o < 32; o <<= 1) {
                        const float nv = __shfl_up_sync(0xffffffffu, pref, o);
                        if (lane >= o) pref += nv;
                    }
                    pos[r] = carry[r] + pref;
                    carry[r] += __shfl_sync(0xffffffffu, pref, 31);
                }
            }

            // ---- online softmax + PV ----
            if (anyw) {
                const int kglob = kb + kkl;
                float p[4];
                #pragma unroll
                for (int r = 0; r < 4; r++) {
                    const int qr = wq0g + r;
                    const bool rowactive = (kb <= qr);      // warp-uniform
                    float s = -1e30f;
                    if (rowactive && kglob <= qr) {
                        s = dot[r] * SCALE;
                        if (need_gate) {
                            const float pc  = fminf(pos[r], (float)(SS-1));
                            const float pf  = floorf(pc);
                            const int   ic  = (int)ceilf(pc);
                            const int   ifl = (int)pf;
                            const float wf  = pc - pf;
                            const float* cr = &Csm[(wq0l + r)*SS];
                            s += cr[ic]*wf + cr[ifl]*(1.f - wf);
                        }
                    }
                    float tmax = s;
                    #pragma unroll
                    for (int o = 16; o; o >>= 1)
                        tmax = fmaxf(tmax, __shfl_xor_sync(0xffffffffu, tmax, o));
                    if (rowactive) {
                        const float mnew  = fmaxf(m[r], tmax);
                        const float alpha = __expf(m[r] - mnew);
                        const float pr    = __expf(s - mnew);   // 0 for masked lanes
                        float ps = pr;
                        #pragma unroll
                        for (int o = 16; o; o >>= 1)
                            ps += __shfl_xor_sync(0xffffffffu, ps, o);
                        l[r] = l[r]*alpha + ps;
                        acc[r][0] *= alpha; acc[r][1] *= alpha;
                        m[r] = mnew;
                        p[r] = pr;
                    } else {
                        p[r] = 0.f;
                    }
                }

                *(float4*)&Psm[w][kkl][0] = make_float4(p[0], p[1], p[2], p[3]);
                __syncwarp();
                const int d2 = 2*lane;
                #pragma unroll 8
                for (int kk = 0; kk < 32; kk++) {
                    const float4 pv = *(const float4*)&Psm[w][kk][0];  // broadcast
                    const float2 vv = *(const float2*)&Vsm[kk*DK + d2];
                    acc[0][0] += pv.x*vv.x; acc[0][1] += pv.x*vv.y;
                    acc[1][0] += pv.y*vv.x; acc[1][1] += pv.y*vv.y;
                    acc[2][0] += pv.z*vv.x; acc[2][1] += pv.z*vv.y;
                    acc[3][0] += pv.w*vv.x; acc[3][1] += pv.w*vv.y;
                }
                __syncwarp();
            }
        }
    }

    #pragma unroll
    for (int r = 0; r < 4; r++) {
        const float inv = 1.f / l[r];
        float2 o2; o2.x = acc[r][0]*inv; o2.y = acc[r][1]*inv;
        *(float2*)&out[(size_t)(bL + wq0g + r)*DK + 2*lane] = o2;
    }
}

// ---------------------------------------------------------------------------
extern "C" void kernel_launch(void* const* d_in, const int* in_sizes, int n_in,
                              void* d_out, int out_size)
{
    const float* x    = (const float*)d_in[0];
    const float* Wq   = (const float*)d_in[1];
    const float* Wk   = (const float*)d_in[2];
    const float* Wv   = (const float*)d_in[3];
    const float* Wqs  = (const float*)d_in[4];
    const float* Wks  = (const float*)d_in[5];
    const float* Wvs  = (const float*)d_in[6];
    const float* Wqe  = (const float*)d_in[7];
    const float* Wke  = (const float*)d_in[8];
    const float* Wve  = (const float*)d_in[9];
    const float* lg   = (const float*)d_in[10];
    const float* lb   = (const float*)d_in[11];
    const float* lsg  = (const float*)d_in[12];
    const float* lsb  = (const float*)d_in[13];
    const float* leg  = (const float*)d_in[14];
    const float* leb  = (const float*)d_in[15];
    const float* cope = (const float*)d_in[16];
    float* out = (float*)d_out;

    ln_proj_kernel<<<NROW/RPC, 256>>>(x, Wq, Wk, Wv, Wqs, Wks, Wvs, Wqe, Wke, Wve,
                                      lg, lb, lsg, lsb, leg, leb);
    attn_kernel<<<dim3(LL/32, BB), 256>>>(cope, out);
}

// round 10
// speedup vs baseline: 2.0674x; 1.1504x over previous
#include <cuda_runtime.h>
#include <math.h>

// Problem constants
#define BB    4
#define SS    128
#define LL    2304          // SEQ + 2S
#define DIN   512
#define DK    64
#define NROW  (BB*LL)       // 9216
#define MIDLO SS            // 128
#define MIDHI (LL-SS)       // 2176
#define SCALE 0.125f        // 1/sqrt(64)

// Scratch: projected Q/K/V for all rows
__device__ float g_Q[NROW*DK];
__device__ float g_K[NROW*DK];
__device__ float g_V[NROW*DK];

// ---------------------------------------------------------------------------
// Kernel 1: LayerNorm + QKV projection. 16 rows per CTA, float4 xn reads.
// ---------------------------------------------------------------------------
#define RPC 16
__global__ __launch_bounds__(256) void ln_proj_kernel(
    const float* __restrict__ x,
    const float* __restrict__ Wq,  const float* __restrict__ Wk,  const float* __restrict__ Wv,
    const float* __restrict__ Wqs, const float* __restrict__ Wks, const float* __restrict__ Wvs,
    const float* __restrict__ Wqe, const float* __restrict__ Wke, const float* __restrict__ Wve,
    const float* __restrict__ lg,  const float* __restrict__ lb,
    const float* __restrict__ lsg, const float* __restrict__ lsb,
    const float* __restrict__ leg, const float* __restrict__ leb)
{
    __shared__ float xn[RPC*DIN];                // 32 KB normalized rows
    const int tid  = threadIdx.x;
    const int w    = tid >> 5;
    const int lane = tid & 31;
    const int r0   = blockIdx.x * RPC;           // segment bounds are %16 == 0
    const int rloc = r0 % LL;
    const int seg  = (rloc < SS) ? 1 : (rloc >= MIDHI ? 2 : 0);

    const float* g  = seg==0 ? lg : (seg==1 ? lsg : leg);
    const float* be = seg==0 ? lb : (seg==1 ? lsb : leb);

    // --- LayerNorm: warp w handles rows 2w, 2w+1 ---
    #pragma unroll
    for (int rr = 0; rr < 2; rr++) {
        const int rl = w*2 + rr;
        const float* xr = x + (size_t)(r0 + rl) * DIN;
        float s = 0.f, s2 = 0.f;
        for (int i = lane; i < DIN; i += 32) { float v = xr[i]; s += v; s2 += v*v; }
        #pragma unroll
        for (int o = 16; o; o >>= 1) {
            s  += __shfl_xor_sync(0xffffffffu, s,  o);
            s2 += __shfl_xor_sync(0xffffffffu, s2, o);
        }
        const float mean = s * (1.0f/DIN);
        const float var  = s2 * (1.0f/DIN) - mean*mean;
        const float rstd = rsqrtf(var + 1e-5f);
        for (int i = lane; i < DIN; i += 32)
            xn[rl*DIN + i] = (xr[i] - mean) * rstd * g[i] + be[i];
    }
    __syncthreads();

    // --- Projections: 192 output columns, 16 rows each ---
    if (tid < 192) {
        const float* W; float* dst; int col;
        if (tid < 64)       { W = seg==0 ? Wq : (seg==1 ? Wqs : Wqe); dst = g_Q; col = tid; }
        else if (tid < 128) { W = seg==0 ? Wk : (seg==1 ? Wks : Wke); dst = g_K; col = tid - 64; }
        else                { W = seg==0 ? Wv : (seg==1 ? Wvs : Wve); dst = g_V; col = tid - 128; }

        float acc[RPC];
        #pragma unroll
        for (int r = 0; r < RPC; r++) acc[r] = 0.f;

        for (int i4 = 0; i4 < DIN/4; i4++) {
            const int i = i4 * 4;
            const float w0 = W[(i+0)*DK + col];   // coalesced across lanes
            const float w1 = W[(i+1)*DK + col];
            const float w2 = W[(i+2)*DK + col];
            const float w3 = W[(i+3)*DK + col];
            #pragma unroll
            for (int r = 0; r < RPC; r++) {
                const float4 x4 = *(const float4*)&xn[r*DIN + i];   // LDS.128 broadcast
                acc[r] += x4.x*w0 + x4.y*w1 + x4.z*w2 + x4.w*w3;
            }
        }
        #pragma unroll
        for (int r = 0; r < RPC; r++) dst[(size_t)(r0 + r)*DK + col] = acc[r];
    }
}

// ---------------------------------------------------------------------------
// Kernel 2: fused CoPE-gated causal attention, register-tiled.
//  - CTA: 32 q rows; warp = 4 q rows; 256 threads.
//  - HEAVY-FIRST CTA order: blockIdx.x=0 -> highest q0 (most tiles) so the
//    long CTAs start in wave 1 and light CTAs backfill the tail.
//  - k-tiles of 32 in DESCENDING order (reverse cumsum of gates = carry +
//    warp inclusive prefix over lanes, lane order = descending k).
//  - FIXED-SHIFT softmax (no online max): scores are bounded (|bias|<~25,
//    exp fits fp32 with huge margin), and softmax is shift-invariant, so
//    p = exp(s), l accumulated PER LANE, single reduce at the end. Removes
//    all per-tile reduction shuffles + alpha rescales.
// ---------------------------------------------------------------------------
#define KROW 68                       // padded K row (floats): conflict-free LDS.128
__global__ __launch_bounds__(256, 3) void attn_kernel(
    const float* __restrict__ cope,   // [64][128] row-major
    float* __restrict__ out)          // [B][L][64]
{
    __shared__ float Ksm[32*KROW];    // K tile [kk][d], padded        (8.5 KB)
    __shared__ float Vsm[32*DK];      // V tile [kk][d]                (8 KB)
    __shared__ float Qs [32*DK];      // 32 q rows                     (8 KB)
    __shared__ float Csm[32*SS];      // cope logits per q row         (16 KB)
    __shared__ float Psm[8][32][4];   // [warp][kk][r] prob strip      (4 KB)

    const int tid  = threadIdx.x;
    const int w    = tid >> 5;
    const int lane = tid & 31;
    const int b    = blockIdx.y;
    const int q0   = (gridDim.x - 1 - blockIdx.x) * 32;   // heavy-first
    const int bL   = b * LL;
    const bool midq = (q0 >= MIDLO) && (q0 < MIDHI);   // uniform within CTA
    const int wq0l  = w * 4;             // first local q row of this warp
    const int wq0g  = q0 + wq0l;         // first global q row of this warp
    const int qg3   = wq0g + 3;          // last q row of this warp
    const int qmaxc = q0 + 31;           // last q row of CTA

    // Load Q tile (32x64 floats = 512 float4)
    for (int i = tid; i < 512; i += 256) {
        const int row = i >> 4, d4 = (i & 15) << 2;
        *(float4*)&Qs[row*DK + d4] =
            *(const float4*)&g_Q[(size_t)(bL + q0 + row)*DK + d4];
    }
    __syncthreads();

    // CoPE logits for this warp's 4 rows: Csm[r][j] = q_r . cope[:, j]
    if (midq) {
        float4 ca[4] = {{0,0,0,0},{0,0,0,0},{0,0,0,0},{0,0,0,0}};
        const int j4 = lane * 4;
        #pragma unroll 4
        for (int d = 0; d < DK; d++) {
            const float4 cv = *(const float4*)&cope[d*SS + j4];
            #pragma unroll
            for (int r = 0; r < 4; r++) {
                const float qd = Qs[(wq0l + r)*DK + d];
                ca[r].x += qd*cv.x; ca[r].y += qd*cv.y;
                ca[r].z += qd*cv.z; ca[r].w += qd*cv.w;
            }
        }
        #pragma unroll
        for (int r = 0; r < 4; r++)
            *(float4*)&Csm[(wq0l + r)*SS + j4] = ca[r];
    }

    float l[4]     = {0.f,0.f,0.f,0.f};        // per-lane partial softmax denom
    float carry[4] = {0.f,0.f,0.f,0.f};
    float acc[4][2] = {{0.f,0.f},{0.f,0.f},{0.f,0.f},{0.f,0.f}};

    const int t_hi = midq ? (MIDHI/32 - 1) : (qmaxc >> 5);
    const int kkl   = 31 - lane;           // tile-local k, descending across lanes

    for (int t = t_hi; t >= 0; t--) {
        const int  kb       = t * 32;
        const bool tile_mid = (kb >= MIDLO);            // t_hi caps kb < MIDHI
        const bool ctascore = (kb <= qmaxc);

        __syncthreads();                   // protect previous tile's SMEM reads
        for (int i = tid; i < 512; i += 256) {
            const int kk = i >> 4, d4 = (i & 15) << 2;
            *(float4*)&Ksm[kk*KROW + d4] =
                *(const float4*)&g_K[(size_t)(bL + kb + kk)*DK + d4];
            if (ctascore)
                *(float4*)&Vsm[kk*DK + d4] =
                    *(const float4*)&g_V[(size_t)(bL + kb + kk)*DK + d4];
        }
        __syncthreads();

        const bool need_gate = midq && tile_mid;        // gates: ALL middle k (CTA-uniform)
        const bool anyw      = (kb <= qg3);             // warp scores this tile (warp-uniform)

        if (need_gate || anyw) {
            // ---- score dots for 4 rows (K read once, shared by rows) ----
            float dot[4] = {0.f,0.f,0.f,0.f};
            {
                const float4* kp = (const float4*)&Ksm[kkl*KROW];
                #pragma unroll 8
                for (int c = 0; c < 16; c++) {
                    const float4 kv = kp[c];
                    #pragma unroll
                    for (int r = 0; r < 4; r++) {
                        const float4 qv = *(const float4*)&Qs[(wq0l + r)*DK + c*4];
                        dot[r] += kv.x*qv.x + kv.y*qv.y + kv.z*qv.z + kv.w*qv.w;
                    }
                }
            }

            // ---- gate suffix-sum (reverse cumsum over k) ----
            float pos[4] = {0.f,0.f,0.f,0.f};
            if (need_gate) {
                #pragma unroll
                for (int r = 0; r < 4; r++) {
                    const float gg = 1.f / (1.f + __expf(-dot[r]));
                    float pref = gg;
                    #pragma unroll
                    for (int o = 1; o < 32; o <<= 1) {
                        const float nv = __shfl_up_sync(0xffffffffu, pref, o);
                        if (lane >= o) pref += nv;
                    }
                    pos[r] = carry[r] + pref;
                    carry[r] += __shfl_sync(0xffffffffu, pref, 31);
                }
            }

            // ---- fixed-shift softmax + PV (no reductions in loop) ----
            if (anyw) {
                const int kglob = kb + kkl;
                float p[4];
                #pragma unroll
                for (int r = 0; r < 4; r++) {
                    const int qr = wq0g + r;
                    float s = -1e30f;
                    if (kglob <= qr) {
                        s = dot[r] * SCALE;
                        if (need_gate) {
                            const float pc  = fminf(pos[r], (float)(SS-1));
                            const float pf  = floorf(pc);
                            const int   ic  = (int)ceilf(pc);
                            const int   ifl = (int)pf;
                            const float wf  = pc - pf;
                            const float* cr = &Csm[(wq0l + r)*SS];
                            s += cr[ic]*wf + cr[ifl]*(1.f - wf);
                        }
                    }
                    p[r] = __expf(s);            // 0 for masked lanes
                    l[r] += p[r];                // per-lane partial denom
                }

                *(float4*)&Psm[w][kkl][0] = make_float4(p[0], p[1], p[2], p[3]);
                __syncwarp();
                const int d2 = 2*lane;
                #pragma unroll 8
                for (int kk = 0; kk < 32; kk++) {
                    const float4 pv = *(const float4*)&Psm[w][kk][0];  // broadcast
                    const float2 vv = *(const float2*)&Vsm[kk*DK + d2];
                    acc[0][0] += pv.x*vv.x; acc[0][1] += pv.x*vv.y;
                    acc[1][0] += pv.y*vv.x; acc[1][1] += pv.y*vv.y;
                    acc[2][0] += pv.z*vv.x; acc[2][1] += pv.z*vv.y;
                    acc[3][0] += pv.w*vv.x; acc[3][1] += pv.w*vv.y;
                }
                __syncwarp();
            }
        }
    }

    // Final: reduce per-lane denominators once, normalize, store.
    #pragma unroll
    for (int r = 0; r < 4; r++) {
        float lr = l[r];
        #pragma unroll
        for (int o = 16; o; o >>= 1) lr += __shfl_xor_sync(0xffffffffu, lr, o);
        const float inv = 1.f / lr;
        float2 o2; o2.x = acc[r][0]*inv; o2.y = acc[r][1]*inv;
        *(float2*)&out[(size_t)(bL + wq0g + r)*DK + 2*lane] = o2;
    }
}

// ---------------------------------------------------------------------------
extern "C" void kernel_launch(void* const* d_in, const int* in_sizes, int n_in,
                              void* d_out, int out_size)
{
    const float* x    = (const float*)d_in[0];
    const float* Wq   = (const float*)d_in[1];
    const float* Wk   = (const float*)d_in[2];
    const float* Wv   = (const float*)d_in[3];
    const float* Wqs  = (const float*)d_in[4];
    const float* Wks  = (const float*)d_in[5];
    const float* Wvs  = (const float*)d_in[6];
    const float* Wqe  = (const float*)d_in[7];
    const float* Wke  = (const float*)d_in[8];
    const float* Wve  = (const float*)d_in[9];
    const float* lg   = (const float*)d_in[10];
    const float* lb   = (const float*)d_in[11];
    const float* lsg  = (const float*)d_in[12];
    const float* lsb  = (const float*)d_in[13];
    const float* leg  = (const float*)d_in[14];
    const float* leb  = (const float*)d_in[15];
    const float* cope = (const float*)d_in[16];
    float* out = (float*)d_out;

    ln_proj_kernel<<<NROW/RPC, 256>>>(x, Wq, Wk, Wv, Wqs, Wks, Wvs, Wqe, Wke, Wve,
                                      lg, lb, lsg, lsb, leg, leb);
    attn_kernel<<<dim3(LL/32, BB), 256>>>(cope, out);
}

// round 11
// speedup vs baseline: 2.3355x; 1.1297x over previous
#include <cuda_runtime.h>
#include <math.h>

// Problem constants
#define BB    4
#define SS    128
#define LL    2304          // SEQ + 2S
#define DIN   512
#define DK    64
#define NROW  (BB*LL)       // 9216
#define MIDLO SS            // 128
#define MIDHI (LL-SS)       // 2176
#define SCALE 0.125f        // 1/sqrt(64)

// Scratch: projected Q/K/V for all rows
__device__ float g_Q[NROW*DK];
__device__ float g_K[NROW*DK];
__device__ float g_V[NROW*DK];

// ---------------------------------------------------------------------------
// Kernel 1: LayerNorm + QKV projection. 16 rows per CTA, float4 xn reads.
// ---------------------------------------------------------------------------
#define RPC 16
__global__ __launch_bounds__(256) void ln_proj_kernel(
    const float* __restrict__ x,
    const float* __restrict__ Wq,  const float* __restrict__ Wk,  const float* __restrict__ Wv,
    const float* __restrict__ Wqs, const float* __restrict__ Wks, const float* __restrict__ Wvs,
    const float* __restrict__ Wqe, const float* __restrict__ Wke, const float* __restrict__ Wve,
    const float* __restrict__ lg,  const float* __restrict__ lb,
    const float* __restrict__ lsg, const float* __restrict__ lsb,
    const float* __restrict__ leg, const float* __restrict__ leb)
{
    __shared__ float xn[RPC*DIN];                // 32 KB normalized rows
    const int tid  = threadIdx.x;
    const int w    = tid >> 5;
    const int lane = tid & 31;
    const int r0   = blockIdx.x * RPC;           // segment bounds are %16 == 0
    const int rloc = r0 % LL;
    const int seg  = (rloc < SS) ? 1 : (rloc >= MIDHI ? 2 : 0);

    const float* g  = seg==0 ? lg : (seg==1 ? lsg : leg);
    const float* be = seg==0 ? lb : (seg==1 ? lsb : leb);

    // --- LayerNorm: warp w handles rows 2w, 2w+1 ---
    #pragma unroll
    for (int rr = 0; rr < 2; rr++) {
        const int rl = w*2 + rr;
        const float* xr = x + (size_t)(r0 + rl) * DIN;
        float s = 0.f, s2 = 0.f;
        for (int i = lane; i < DIN; i += 32) { float v = xr[i]; s += v; s2 += v*v; }
        #pragma unroll
        for (int o = 16; o; o >>= 1) {
            s  += __shfl_xor_sync(0xffffffffu, s,  o);
            s2 += __shfl_xor_sync(0xffffffffu, s2, o);
        }
        const float mean = s * (1.0f/DIN);
        const float var  = s2 * (1.0f/DIN) - mean*mean;
        const float rstd = rsqrtf(var + 1e-5f);
        for (int i = lane; i < DIN; i += 32)
            xn[rl*DIN + i] = (xr[i] - mean) * rstd * g[i] + be[i];
    }
    __syncthreads();

    // --- Projections: 192 output columns, 16 rows each ---
    if (tid < 192) {
        const float* W; float* dst; int col;
        if (tid < 64)       { W = seg==0 ? Wq : (seg==1 ? Wqs : Wqe); dst = g_Q; col = tid; }
        else if (tid < 128) { W = seg==0 ? Wk : (seg==1 ? Wks : Wke); dst = g_K; col = tid - 64; }
        else                { W = seg==0 ? Wv : (seg==1 ? Wvs : Wve); dst = g_V; col = tid - 128; }

        float acc[RPC];
        #pragma unroll
        for (int r = 0; r < RPC; r++) acc[r] = 0.f;

        for (int i4 = 0; i4 < DIN/4; i4++) {
            const int i = i4 * 4;
            const float w0 = W[(i+0)*DK + col];   // coalesced across lanes
            const float w1 = W[(i+1)*DK + col];
            const float w2 = W[(i+2)*DK + col];
            const float w3 = W[(i+3)*DK + col];
            #pragma unroll
            for (int r = 0; r < RPC; r++) {
                const float4 x4 = *(const float4*)&xn[r*DIN + i];   // LDS.128 broadcast
                acc[r] += x4.x*w0 + x4.y*w1 + x4.z*w2 + x4.w*w3;
            }
        }
        #pragma unroll
        for (int r = 0; r < RPC; r++) dst[(size_t)(r0 + r)*DK + col] = acc[r];
    }
}

// ---------------------------------------------------------------------------
// Kernel 2: fused CoPE-gated causal attention, register-tiled + saturation.
//  - CTA: 32 q rows; warp = 4 q rows; 256 threads; heavy-first CTA order.
//  - k-tiles of 32 DESCENDING. pos = min(suffix_sum(gate), 127): suffix sum
//    grows as k decreases, so once carry >= 127 for every row, ALL remaining
//    k have pos == 127.0 EXACTLY -> bias = Csm[row][127] (constant).
//  - Phase 1: full gate+scan body until CTA-wide saturation vote passes.
//  - Phase 2: causal tiles only, lean body (dot, +c127 bias, exp, PV).
//    Gate-only tiles above the diagonal are skipped entirely after saturation.
//  - Fixed-shift softmax (shift-invariant; scores bounded), per-lane denom.
// ---------------------------------------------------------------------------
#define KROW 68                       // padded K row (floats): conflict-free LDS.128
__global__ __launch_bounds__(256, 3) void attn_kernel(
    const float* __restrict__ cope,   // [64][128] row-major
    float* __restrict__ out)          // [B][L][64]
{
    __shared__ float Ksm[32*KROW];    // K tile [kk][d], padded        (8.5 KB)
    __shared__ float Vsm[32*DK];      // V tile [kk][d]                (8 KB)
    __shared__ float Qs [32*DK];      // 32 q rows                     (8 KB)
    __shared__ float Csm[32*SS];      // cope logits per q row         (16 KB)
    __shared__ float Psm[8][32][4];   // [warp][kk][r] prob strip      (4 KB)

    const int tid  = threadIdx.x;
    const int w    = tid >> 5;
    const int lane = tid & 31;
    const int b    = blockIdx.y;
    const int q0   = (gridDim.x - 1 - blockIdx.x) * 32;   // heavy-first
    const int bL   = b * LL;
    const bool midq = (q0 >= MIDLO) && (q0 < MIDHI);   // uniform within CTA
    const int wq0l  = w * 4;             // first local q row of this warp
    const int wq0g  = q0 + wq0l;         // first global q row of this warp
    const int qg3   = wq0g + 3;          // last q row of this warp
    const int qmaxc = q0 + 31;           // last q row of CTA

    // Load Q tile (32x64 floats = 512 float4)
    for (int i = tid; i < 512; i += 256) {
        const int row = i >> 4, d4 = (i & 15) << 2;
        *(float4*)&Qs[row*DK + d4] =
            *(const float4*)&g_Q[(size_t)(bL + q0 + row)*DK + d4];
    }
    __syncthreads();

    // CoPE logits for this warp's 4 rows: Csm[r][j] = q_r . cope[:, j]
    float c127[4] = {0.f,0.f,0.f,0.f};   // Csm[row][127], the saturated bias
    if (midq) {
        float4 ca[4] = {{0,0,0,0},{0,0,0,0},{0,0,0,0},{0,0,0,0}};
        const int j4 = lane * 4;
        #pragma unroll 4
        for (int d = 0; d < DK; d++) {
            const float4 cv = *(const float4*)&cope[d*SS + j4];
            #pragma unroll
            for (int r = 0; r < 4; r++) {
                const float qd = Qs[(wq0l + r)*DK + d];
                ca[r].x += qd*cv.x; ca[r].y += qd*cv.y;
                ca[r].z += qd*cv.z; ca[r].w += qd*cv.w;
            }
        }
        #pragma unroll
        for (int r = 0; r < 4; r++) {
            *(float4*)&Csm[(wq0l + r)*SS + j4] = ca[r];
            c127[r] = __shfl_sync(0xffffffffu, ca[r].w, 31);  // j=127 lives in lane31 .w
        }
    }

    float l[4]     = {0.f,0.f,0.f,0.f};        // per-lane partial softmax denom
    float carry[4] = {0.f,0.f,0.f,0.f};
    float acc[4][2] = {{0.f,0.f},{0.f,0.f},{0.f,0.f},{0.f,0.f}};

    const int kkl   = 31 - lane;           // tile-local k, descending across lanes
    const int t_cau = qmaxc >> 5;          // last tile index with any causal score
    int t = midq ? (MIDHI/32 - 1) : t_cau;

    // ================= Phase 1: gate region (mid CTAs only) =================
    if (midq) {
        for (; t >= 0; t--) {
            // Saturation vote doubles as the tile barrier. Once every row of
            // every warp has carry >= 127, all remaining pos clamp to 127.
            const bool wsat = (carry[0] >= 127.f) & (carry[1] >= 127.f) &
                              (carry[2] >= 127.f) & (carry[3] >= 127.f);
            if (__syncthreads_and(wsat)) break;

            const int  kb       = t * 32;
            const bool tile_mid = (kb >= MIDLO);
            const bool ctascore = (kb <= qmaxc);

            for (int i = tid; i < 512; i += 256) {
                const int kk = i >> 4, d4 = (i & 15) << 2;
                *(float4*)&Ksm[kk*KROW + d4] =
                    *(const float4*)&g_K[(size_t)(bL + kb + kk)*DK + d4];
                if (ctascore)
                    *(float4*)&Vsm[kk*DK + d4] =
                        *(const float4*)&g_V[(size_t)(bL + kb + kk)*DK + d4];
            }
            __syncthreads();

            const bool need_gate = tile_mid;
            const bool anyw      = (kb <= qg3);

            if (need_gate || anyw) {
                float dot[4] = {0.f,0.f,0.f,0.f};
                {
                    const float4* kp = (const float4*)&Ksm[kkl*KROW];
                    #pragma unroll 8
                    for (int c = 0; c < 16; c++) {
                        const float4 kv = kp[c];
                        #pragma unroll
                        for (int r = 0; r < 4; r++) {
                            const float4 qv = *(const float4*)&Qs[(wq0l + r)*DK + c*4];
                            dot[r] += kv.x*qv.x + kv.y*qv.y + kv.z*qv.z + kv.w*qv.w;
                        }
                    }
                }

                float pos[4] = {0.f,0.f,0.f,0.f};
                if (need_gate) {
                    #pragma unroll
                    for (int r = 0; r < 4; r++) {
                        const float gg = 1.f / (1.f + __expf(-dot[r]));
                        float pref = gg;
                        #pragma unroll
                        for (int o = 1; o < 32; o <<= 1) {
                            const float nv = __shfl_up_sync(0xffffffffu, pref, o);
                            if (lane >= o) pref += nv;
                        }
                        pos[r] = carry[r] + pref;
                        carry[r] += __shfl_sync(0xffffffffu, pref, 31);
                    }
                }

                if (anyw) {
                    const int kglob = kb + kkl;
                    float p[4];
                    #pragma unroll
                    for (int r = 0; r < 4; r++) {
                        const int qr = wq0g + r;
                        float s = -1e30f;
                        if (kglob <= qr) {
                            s = dot[r] * SCALE;
                            if (need_gate) {
                                const float pc  = fminf(pos[r], (float)(SS-1));
                                const float pf  = floorf(pc);
                                const int   ic  = (int)ceilf(pc);
                                const int   ifl = (int)pf;
                                const float wf  = pc - pf;
                                const float* cr = &Csm[(wq0l + r)*SS];
                                s += cr[ic]*wf + cr[ifl]*(1.f - wf);
                            }
                        }
                        p[r] = __expf(s);
                        l[r] += p[r];
                    }

                    *(float4*)&Psm[w][kkl][0] = make_float4(p[0], p[1], p[2], p[3]);
                    __syncwarp();
                    const int d2 = 2*lane;
                    #pragma unroll 8
                    for (int kk = 0; kk < 32; kk++) {
                        const float4 pv = *(const float4*)&Psm[w][kk][0];
                        const float2 vv = *(const float2*)&Vsm[kk*DK + d2];
                        acc[0][0] += pv.x*vv.x; acc[0][1] += pv.x*vv.y;
                        acc[1][0] += pv.y*vv.x; acc[1][1] += pv.y*vv.y;
                        acc[2][0] += pv.z*vv.x; acc[2][1] += pv.z*vv.y;
                        acc[3][0] += pv.w*vv.x; acc[3][1] += pv.w*vv.y;
                    }
                    __syncwarp();
                }
            }
        }
    }

    // ============ Phase 2: causal-only tiles, saturated bias = c127 ==========
    for (int t2 = (t < t_cau ? t : t_cau); t2 >= 0; t2--) {
        const int  kb       = t2 * 32;
        const bool tile_mid = midq && (kb >= MIDLO);   // bias applies (exact 127-clamp)

        __syncthreads();
        for (int i = tid; i < 512; i += 256) {
            const int kk = i >> 4, d4 = (i & 15) << 2;
            *(float4*)&Ksm[kk*KROW + d4] =
                *(const float4*)&g_K[(size_t)(bL + kb + kk)*DK + d4];
            *(float4*)&Vsm[kk*DK + d4] =
                *(const float4*)&g_V[(size_t)(bL + kb + kk)*DK + d4];
        }
        __syncthreads();

        if (kb <= qg3) {
            float dot[4] = {0.f,0.f,0.f,0.f};
            {
                const float4* kp = (const float4*)&Ksm[kkl*KROW];
                #pragma unroll 8
                for (int c = 0; c < 16; c++) {
                    const float4 kv = kp[c];
                    #pragma unroll
                    for (int r = 0; r < 4; r++) {
                        const float4 qv = *(const float4*)&Qs[(wq0l + r)*DK + c*4];
                        dot[r] += kv.x*qv.x + kv.y*qv.y + kv.z*qv.z + kv.w*qv.w;
                    }
                }
            }

            const int kglob = kb + kkl;
            float p[4];
            #pragma unroll
            for (int r = 0; r < 4; r++) {
                const int qr = wq0g + r;
                float s = -1e30f;
                if (kglob <= qr) {
                    s = dot[r] * SCALE;
                    if (tile_mid) s += c127[r];
                }
                p[r] = __expf(s);
                l[r] += p[r];
            }

            *(float4*)&Psm[w][kkl][0] = make_float4(p[0], p[1], p[2], p[3]);
            __syncwarp();
            const int d2 = 2*lane;
            #pragma unroll 8
            for (int kk = 0; kk < 32; kk++) {
                const float4 pv = *(const float4*)&Psm[w][kk][0];
                const float2 vv = *(const float2*)&Vsm[kk*DK + d2];
                acc[0][0] += pv.x*vv.x; acc[0][1] += pv.x*vv.y;
                acc[1][0] += pv.y*vv.x; acc[1][1] += pv.y*vv.y;
                acc[2][0] += pv.z*vv.x; acc[2][1] += pv.z*vv.y;
                acc[3][0] += pv.w*vv.x; acc[3][1] += pv.w*vv.y;
            }
            __syncwarp();
        }
    }

    // Final: reduce per-lane denominators once, normalize, store.
    #pragma unroll
    for (int r = 0; r < 4; r++) {
        float lr = l[r];
        #pragma unroll
        for (int o = 16; o; o >>= 1) lr += __shfl_xor_sync(0xffffffffu, lr, o);
        const float inv = 1.f / lr;
        float2 o2; o2.x = acc[r][0]*inv; o2.y = acc[r][1]*inv;
        *(float2*)&out[(size_t)(bL + wq0g + r)*DK + 2*lane] = o2;
    }
}

// ---------------------------------------------------------------------------
extern "C" void kernel_launch(void* const* d_in, const int* in_sizes, int n_in,
                              void* d_out, int out_size)
{
    const float* x    = (const float*)d_in[0];
    const float* Wq   = (const float*)d_in[1];
    const float* Wk   = (const float*)d_in[2];
    const float* Wv   = (const float*)d_in[3];
    const float* Wqs  = (const float*)d_in[4];
    const float* Wks  = (const float*)d_in[5];
    const float* Wvs  = (const float*)d_in[6];
    const float* Wqe  = (const float*)d_in[7];
    const float* Wke  = (const float*)d_in[8];
    const float* Wve  = (const float*)d_in[9];
    const float* lg   = (const float*)d_in[10];
    const float* lb   = (const float*)d_in[11];
    const float* lsg  = (const float*)d_in[12];
    const float* lsb  = (const float*)d_in[13];
    const float* leg  = (const float*)d_in[14];
    const float* leb  = (const float*)d_in[15];
    const float* cope = (const float*)d_in[16];
    float* out = (float*)d_out;

    ln_proj_kernel<<<NROW/RPC, 256>>>(x, Wq, Wk, Wv, Wqs, Wks, Wvs, Wqe, Wke, Wve,
                                      lg, lb, lsg, lsb, leg, leb);
    attn_kernel<<<dim3(LL/32, BB), 256>>>(cope, out);
}